// round 16
// baseline (speedup 1.0000x reference)
#include <cuda_runtime.h>
#include <cuda_bf16.h>
#include <cstdint>

// Problem constants
#define BATCH 16
#define CIN   64
#define COUT  128
#define L     1024
#define KTAPS 9

#define NBLK  128
#define NTHR  1024

// ---- device scratch (zero-init at load; monotone/idempotent across replays) --
__device__ unsigned g_mx;      // atomicMax |x| bits
__device__ unsigned g_mw;      // atomicMax |w| bits
__device__ unsigned g_ccw;     // +18 per launch
__device__ unsigned g_ccx;     // +128 per launch (also round ticket)
__device__ unsigned g_ccq;     // +128 per launch
__device__ signed char g_qw[KTAPS*COUT*CIN];   // [tap][cout][cin]

#define VREAD(x) (*(volatile unsigned*)&(x))

// ---------------------------------------------------------------------------
// smem: Bs [0,92160) | qwin [92160,109440) | fbuf [109440,158592)
// epilogue smf reuses [0,67584)
// ---------------------------------------------------------------------------
#define ROWB 80
#define BS_BYTES (KTAPS*COUT*ROWB)        // 92160
#define QWIN_OFF BS_BYTES
#define QROW 2880                         // 36*80
#define QWIN_BYTES (6*QROW)               // 17280
#define FBUF_OFF (QWIN_OFF + QWIN_BYTES)  // 109440
#define FBUF_BYTES 49152
#define SMEM_TOT (FBUF_OFF + FBUF_BYTES)  // 158592
#define EP_STRIDE 132

__device__ __forceinline__ void mma_s8(int d[4], const unsigned a[4],
                                       unsigned b0, unsigned b1) {
    asm volatile(
      "mma.sync.aligned.m16n8k32.row.col.s32.s8.s8.s32 "
      "{%0,%1,%2,%3}, {%4,%5,%6,%7}, {%8,%9}, {%0,%1,%2,%3};\n"
      : "+r"(d[0]), "+r"(d[1]), "+r"(d[2]), "+r"(d[3])
      : "r"(a[0]), "r"(a[1]), "r"(a[2]), "r"(a[3]), "r"(b0), "r"(b1));
}
__device__ __forceinline__ void cp16(void* smem, const void* g) {
    unsigned s = (unsigned)__cvta_generic_to_shared(smem);
    asm volatile("cp.async.cg.shared.global [%0], [%1], 16;\n" :: "r"(s), "l"(g));
}
__device__ __forceinline__ uint32_t smem_u32(const void* p) {
    uint32_t a;
    asm("{ .reg .u64 t; cvta.to.shared.u64 t, %1; cvt.u32.u64 %0, t; }"
        : "=r"(a) : "l"(p));
    return a;
}
__device__ __forceinline__ void ldsm4(unsigned a[4], uint32_t addr) {
    asm volatile("ldmatrix.sync.aligned.m8n8.x4.shared.b16 {%0,%1,%2,%3}, [%4];"
        : "=r"(a[0]), "=r"(a[1]), "=r"(a[2]), "=r"(a[3]) : "r"(addr));
}
__device__ __forceinline__ void ldsm2(unsigned b[2], uint32_t addr) {
    asm volatile("ldmatrix.sync.aligned.m8n8.x2.shared.b16 {%0,%1}, [%2];"
        : "=r"(b[0]), "=r"(b[1]) : "r"(addr));
}

__global__ void __launch_bounds__(NTHR, 1)
kfused(const float* __restrict__ x, const float* __restrict__ w,
       const float* __restrict__ bias, float* __restrict__ out) {
    extern __shared__ char sm[];
    __shared__ float srx[32], srw[32], s_sc[2];
    __shared__ unsigned s_round;

    const int tid  = threadIdx.x;
    const int wid  = tid >> 5;
    const int lane = tid & 31;
    const int bl   = blockIdx.x;

    const int bi    = bl >> 3;
    const int ytile = bl & 7;
    const int l0    = ytile * 128;
    const int y0    = ytile * 4 - 1;

    char*  Bs   = sm;
    char*  qwin = sm + QWIN_OFF;
    float* fbuf = reinterpret_cast<float*>(sm + FBUF_OFF);   // [64][6][32]

    // -------- phase 1a: w stripe max (blocks 0..17), arrive ccw EARLY -------
    {
        float mw = 0.f;
        if (bl < 18) {
            float4 v = reinterpret_cast<const float4*>(w)[bl*NTHR + tid];
            mw = fmaxf(fmaxf(fabsf(v.x), fabsf(v.y)),
                       fmaxf(fabsf(v.z), fabsf(v.w)));
        }
        #pragma unroll
        for (int o = 16; o; o >>= 1) mw = fmaxf(mw, __shfl_xor_sync(~0u, mw, o));
        if (lane == 0) srw[wid] = mw;
        __syncthreads();
        if (tid < 32) {
            mw = srw[tid];
            #pragma unroll
            for (int o = 16; o; o >>= 1) mw = fmaxf(mw, __shfl_xor_sync(~0u, mw, o));
            if (tid == 0 && bl < 18) {
                atomicMax(&g_mw, __float_as_uint(mw));
                __threadfence();
                atomicAdd(&g_ccw, 1u);
            }
        }
    }

    // -------- phase 1b: x window -> fbuf (+global max|x|), zero qwin --------
    {
        int4* q4 = reinterpret_cast<int4*>(qwin);
        for (int i = tid; i < QWIN_BYTES/16; i += NTHR)
            q4[i] = make_int4(0,0,0,0);

        const float4* x4 = reinterpret_cast<const float4*>(x);
        float4* f4 = reinterpret_cast<float4*>(fbuf);
        float mx = 0.f;
        #pragma unroll
        for (int u = 0; u < 3; u++) {
            const int idx = u*NTHR + tid;          // 0..3071
            const int seg = idx >> 3, q = idx & 7;
            const int c = seg / 6, yy = seg - c*6;
            const int gy = y0 + yy;
            float4 v = make_float4(0.f,0.f,0.f,0.f);
            if ((unsigned)gy < 32u)
                v = x4[(((bi*CIN + c) << 5) + gy)*8 + q];
            f4[idx] = v;
            mx = fmaxf(mx, fmaxf(fmaxf(fabsf(v.x), fabsf(v.y)),
                                 fmaxf(fabsf(v.z), fabsf(v.w))));
        }
        #pragma unroll
        for (int o = 16; o; o >>= 1) mx = fmaxf(mx, __shfl_xor_sync(~0u, mx, o));
        if (lane == 0) srx[wid] = mx;
        __syncthreads();
        if (tid < 32) {
            mx = srx[tid];
            #pragma unroll
            for (int o = 16; o; o >>= 1) mx = fmaxf(mx, __shfl_xor_sync(~0u, mx, o));
            if (tid == 0) {
                atomicMax(&g_mx, __float_as_uint(mx));
                __threadfence();
                unsigned tx = atomicAdd(&g_ccx, 1u);
                s_round = tx >> 7;
            }
        }
        __syncthreads();
    }
    const unsigned r = s_round;

    // -------- phase 1c: wait ccw (18 producers, fast), quantize w slice -----
    if (tid == 0) {
        while (VREAD(g_ccw) < (r + 1u) * 18u) {}
        __threadfence();
        s_sc[1] = __uint_as_float(VREAD(g_mw));
    }
    __syncthreads();
    const float fmw = s_sc[1];
    const float invw = __fdiv_rn(127.0f, fmw);
    if (tid < 144) {                               // 144 char4 units per block
        const int unit = bl*144 + tid;             // 0..18431
        const int cin4 = unit & 15;
        const int rem  = unit >> 4;
        const int cout = rem & 127;
        const int tap  = rem >> 7;
        char4 q;
        #pragma unroll
        for (int j = 0; j < 4; j++) {
            float rv = rintf(w[(cout*CIN + cin4*4 + j)*KTAPS + tap] * invw);
            rv = fminf(fmaxf(rv, -127.f), 127.f);
            ((signed char*)&q)[j] = (signed char)(int)rv;
        }
        *reinterpret_cast<char4*>(g_qw + (tap*COUT + cout)*CIN + cin4*4) = q;
    }
    __syncthreads();
    if (tid == 0) { __threadfence(); atomicAdd(&g_ccq, 1u); }

    // -------- phase 1d: wait cq, issue Bs staging (flies during cx wait) ----
    if (tid == 0) {
        while (VREAD(g_ccq) < (r + 1u) * 128u) {}
        __threadfence();
    }
    __syncthreads();
    for (int idx = tid; idx < KTAPS*COUT*4; idx += NTHR) {
        const int rr = idx >> 2, q = idx & 3;
        cp16(Bs + rr*ROWB + q*16, g_qw + rr*CIN + q*16);
    }
    asm volatile("cp.async.commit_group;\n");

    // -------- phase 1e: wait cx (the real barrier), quantize x -> qwin ------
    if (tid == 0) {
        while (VREAD(g_ccx) < (r + 1u) * 128u) {}
        __threadfence();
        s_sc[0] = __uint_as_float(VREAD(g_mx));
    }
    __syncthreads();
    const float fmx = s_sc[0];
    const float invx = __fdiv_rn(127.0f, fmx);
    const float oscale = __fmul_rn(__fdiv_rn(fmx, 127.0f), __fdiv_rn(fmw, 127.0f));

    #pragma unroll
    for (int u = 0; u < 3; u++) {
        const int unit = u*NTHR + tid;
        const int c4   = unit / 192;
        const int cell = unit - c4*192;
        const int yy   = cell >> 5, gx = cell & 31;
        const int gy   = y0 + yy;
        if ((unsigned)gy < 32u) {
            char4 q;
            #pragma unroll
            for (int j = 0; j < 4; j++) {
                float rv = rintf(fbuf[(c4*4 + j)*192 + cell] * invx);
                rv = fminf(fmaxf(rv, -127.f), 127.f);
                ((signed char*)&q)[j] = (signed char)(int)rv;
            }
            *reinterpret_cast<unsigned*>(qwin + yy*QROW + (gx+1)*ROWB + c4*4) =
                *reinterpret_cast<unsigned*>(&q);
        }
    }
    asm volatile("cp.async.wait_group 0;\n");
    __syncthreads();                               // Bs + qwin complete

    // -------- phase 3: MMA, 32 warps, warp tile 32x16 -----------------------
    const int g     = lane >> 2;
    const int tg    = lane & 3;
    const int warpM = wid >> 3;     // 0..3 -> 32 rows
    const int warpN = wid & 7;      // 0..7 -> 16 couts

    int acc[2][2][4];
    #pragma unroll
    for (int mi = 0; mi < 2; mi++)
        #pragma unroll
        for (int nb = 0; nb < 2; nb++)
            #pragma unroll
            for (int rr = 0; rr < 4; rr++) acc[mi][nb][rr] = 0;

    const uint32_t aoff = ((lane & 7) + ((lane >> 3) & 1)*8)*ROWB + (lane >> 4)*16;
    const uint32_t boff = (lane & 7)*ROWB + ((lane >> 3) & 1)*16;
    const uint32_t abase = smem_u32(qwin) + (uint32_t)(warpM*QROW) + aoff;
    const uint32_t bbase = smem_u32(Bs) + (uint32_t)(warpN*16*ROWB) + boff;

    #pragma unroll
    for (int tap = 0; tap < KTAPS; tap++) {
        const int kh = tap / 3, kw = tap % 3;
        const uint32_t at = abase + (uint32_t)(kh*QROW + kw*ROWB);
        const uint32_t bt = bbase + (uint32_t)(tap*(COUT*ROWB));
        #pragma unroll
        for (int kk = 0; kk < 2; kk++) {
            const uint32_t ko = kk * 32;
            unsigned a[2][4];
            ldsm4(a[0], at + ko);
            ldsm4(a[1], at + 16*ROWB + ko);
            unsigned b[2][2];
            ldsm2(b[0], bt + ko);
            ldsm2(b[1], bt + 8*ROWB + ko);
            #pragma unroll
            for (int nb = 0; nb < 2; nb++) {
                mma_s8(acc[0][nb], a[0], b[nb][0], b[nb][1]);
                mma_s8(acc[1][nb], a[1], b[nb][0], b[nb][1]);
            }
        }
    }
    __syncthreads();

    // -------- epilogue: smem transpose -> coalesced float4 stores -----------
    float* smf = reinterpret_cast<float*>(sm);
    #pragma unroll
    for (int mi = 0; mi < 2; mi++) {
        #pragma unroll
        for (int nb = 0; nb < 2; nb++) {
            #pragma unroll
            for (int rr = 0; rr < 4; rr++) {
                const int row = warpM*32 + mi*16 + g + ((rr >> 1) * 8);
                const int col = warpN*16 + nb*8 + tg*2 + (rr & 1);
                smf[col*EP_STRIDE + row] = (float)acc[mi][nb][rr];
            }
        }
    }
    __syncthreads();
    {
        float* op = out + (size_t)bi*COUT*L + l0;
        #pragma unroll
        for (int co = 0; co < 4; co++) {
            const int cout = wid*4 + co;
            const float bz = bias[cout];
            const float* sp = smf + cout*EP_STRIDE + lane*4;
            float4 v = make_float4(oscale*sp[0] + bz, oscale*sp[1] + bz,
                                   oscale*sp[2] + bz, oscale*sp[3] + bz);
            *reinterpret_cast<float4*>(op + (size_t)cout*L + lane*4) = v;
        }
    }
}

// ---------------------------------------------------------------------------
extern "C" void kernel_launch(void* const* d_in, const int* in_sizes, int n_in,
                              void* d_out, int out_size) {
    const float* x  = (const float*)d_in[0];   // [16,64,32,32]
    const float* w  = (const float*)d_in[1];   // [128,64,3,3]
    const float* bs = (const float*)d_in[2];   // [128]
    float* out = (float*)d_out;                // [16,128,32,32]

    cudaFuncSetAttribute(kfused, cudaFuncAttributeMaxDynamicSharedMemorySize,
                         SMEM_TOT);
    kfused<<<NBLK, NTHR, SMEM_TOT>>>(x, w, bs, out);
}

// round 17
// speedup vs baseline: 1.0535x; 1.0535x over previous
#include <cuda_runtime.h>
#include <cuda_bf16.h>
#include <cstdint>

// Problem constants
#define BATCH 16
#define CIN   64
#define COUT  128
#define L     1024
#define KTAPS 9

#define NBLK  256            // 2 CTAs per tile (N-halves), 2 CTAs/SM
#define NTHR  512

// ---- device scratch (zero-init at load; monotone/idempotent across replays) --
__device__ unsigned g_mx;      // atomicMax |x| bits
__device__ unsigned g_mw;      // atomicMax |w| bits
__device__ unsigned g_ccw;     // +36 per launch
__device__ unsigned g_ccx;     // +256 per launch (also round ticket)
__device__ unsigned g_ccq;     // +256 per launch
__device__ signed char g_qw[KTAPS*COUT*CIN];   // [tap][cout][cin]

#define VREAD(x) (*(volatile unsigned*)&(x))

// ---------------------------------------------------------------------------
// smem per CTA: Bs [0,46080) | qwin [46080,63360)   (63.4KB -> occ 2)
// epilogue smf (64x132 floats = 33792B) reuses Bs region
// ---------------------------------------------------------------------------
#define ROWB 80
#define BS_BYTES (KTAPS*64*ROWB)          // 46080 (half-N weight tile)
#define QWIN_OFF BS_BYTES
#define QROW 2880                         // 36*80
#define QWIN_BYTES (6*QROW)               // 17280
#define SMEM_TOT (QWIN_OFF + QWIN_BYTES)  // 63360
#define EP_STRIDE 132

__device__ __forceinline__ void mma_s8(int d[4], const unsigned a[4],
                                       unsigned b0, unsigned b1) {
    asm volatile(
      "mma.sync.aligned.m16n8k32.row.col.s32.s8.s8.s32 "
      "{%0,%1,%2,%3}, {%4,%5,%6,%7}, {%8,%9}, {%0,%1,%2,%3};\n"
      : "+r"(d[0]), "+r"(d[1]), "+r"(d[2]), "+r"(d[3])
      : "r"(a[0]), "r"(a[1]), "r"(a[2]), "r"(a[3]), "r"(b0), "r"(b1));
}
__device__ __forceinline__ void cp16(void* smem, const void* g) {
    unsigned s = (unsigned)__cvta_generic_to_shared(smem);
    asm volatile("cp.async.cg.shared.global [%0], [%1], 16;\n" :: "r"(s), "l"(g));
}
__device__ __forceinline__ uint32_t smem_u32(const void* p) {
    uint32_t a;
    asm("{ .reg .u64 t; cvta.to.shared.u64 t, %1; cvt.u32.u64 %0, t; }"
        : "=r"(a) : "l"(p));
    return a;
}
__device__ __forceinline__ void ldsm4(unsigned a[4], uint32_t addr) {
    asm volatile("ldmatrix.sync.aligned.m8n8.x4.shared.b16 {%0,%1,%2,%3}, [%4];"
        : "=r"(a[0]), "=r"(a[1]), "=r"(a[2]), "=r"(a[3]) : "r"(addr));
}
__device__ __forceinline__ void ldsm2(unsigned b[2], uint32_t addr) {
    asm volatile("ldmatrix.sync.aligned.m8n8.x2.shared.b16 {%0,%1}, [%2];"
        : "=r"(b[0]), "=r"(b[1]) : "r"(addr));
}

__global__ void __launch_bounds__(NTHR, 2)
kfused(const float* __restrict__ x, const float* __restrict__ w,
       const float* __restrict__ bias, float* __restrict__ out) {
    extern __shared__ char sm[];
    __shared__ float srx[16], srw[16], s_sc[2];
    __shared__ unsigned s_round;

    const int tid  = threadIdx.x;
    const int wid  = tid >> 5;
    const int lane = tid & 31;
    const int bl   = blockIdx.x;

    const int bi    = bl >> 4;             // batch
    const int ytile = (bl >> 1) & 7;       // 4 image rows
    const int nh    = bl & 1;              // N half (couts 0-63 / 64-127)
    const int l0    = ytile * 128;
    const int y0    = ytile * 4 - 1;

    char* Bs   = sm;
    char* qwin = sm + QWIN_OFF;

    // -------- phase 1a: w stripe max (blocks 0..35), arrive ccw EARLY -------
    {
        float mw = 0.f;
        if (bl < 36) {
            float4 v = reinterpret_cast<const float4*>(w)[bl*NTHR + tid];
            mw = fmaxf(fmaxf(fabsf(v.x), fabsf(v.y)),
                       fmaxf(fabsf(v.z), fabsf(v.w)));
        }
        #pragma unroll
        for (int o = 16; o; o >>= 1) mw = fmaxf(mw, __shfl_xor_sync(~0u, mw, o));
        if (lane == 0) srw[wid] = mw;
        __syncthreads();
        if (tid < 16) {
            mw = srw[tid];
            #pragma unroll
            for (int o = 8; o; o >>= 1) mw = fmaxf(mw, __shfl_xor_sync(0xffffu, mw, o));
            if (tid == 0 && bl < 36) {
                atomicMax(&g_mw, __float_as_uint(mw));
                __threadfence();
                atomicAdd(&g_ccw, 1u);
            }
        }
    }

    // -------- phase 1b: zero qwin; x window -> REGISTERS (+global max) ------
    float xv[6][4];
    {
        int4* q4 = reinterpret_cast<int4*>(qwin);
        for (int i = tid; i < QWIN_BYTES/16; i += NTHR)
            q4[i] = make_int4(0,0,0,0);

        float mx = 0.f;
        #pragma unroll
        for (int u = 0; u < 6; u++) {
            const int unit = u*NTHR + tid;         // 0..3071
            const int c4   = unit / 192;
            const int cell = unit - c4*192;        // yy*32 + gx
            const int yy   = cell >> 5, gx = cell & 31;
            const int gy   = y0 + yy;
            const bool ok  = (unsigned)gy < 32u;
            const float* xp = x + (((bi*CIN + c4*4) << 10) + gy*32 + gx);
            #pragma unroll
            for (int j = 0; j < 4; j++) {
                float v = ok ? xp[j << 10] : 0.f;
                xv[u][j] = v;
                mx = fmaxf(mx, fabsf(v));
            }
        }
        #pragma unroll
        for (int o = 16; o; o >>= 1) mx = fmaxf(mx, __shfl_xor_sync(~0u, mx, o));
        if (lane == 0) srx[wid] = mx;
        __syncthreads();
        if (tid < 16) {
            mx = srx[tid];
            #pragma unroll
            for (int o = 8; o; o >>= 1) mx = fmaxf(mx, __shfl_xor_sync(0xffffu, mx, o));
            if (tid == 0) {
                atomicMax(&g_mx, __float_as_uint(mx));
                __threadfence();
                unsigned tx = atomicAdd(&g_ccx, 1u);
                s_round = tx >> 8;                 // 256 arrivals / launch
            }
        }
        __syncthreads();
    }
    const unsigned r = s_round;

    // -------- phase 1c: wait ccw (fast), quantize w slice -------------------
    if (tid == 0) {
        while (VREAD(g_ccw) < (r + 1u) * 36u) {}
        __threadfence();
        s_sc[1] = __uint_as_float(VREAD(g_mw));
    }
    __syncthreads();
    const float fmw = s_sc[1];
    const float invw = __fdiv_rn(127.0f, fmw);
    if (tid < 72) {                                // 72 char4 units per block
        const int unit = bl*72 + tid;              // 0..18431
        const int cin4 = unit & 15;
        const int rem  = unit >> 4;
        const int cout = rem & 127;
        const int tap  = rem >> 7;
        char4 q;
        #pragma unroll
        for (int j = 0; j < 4; j++) {
            float rv = rintf(w[(cout*CIN + cin4*4 + j)*KTAPS + tap] * invw);
            rv = fminf(fmaxf(rv, -127.f), 127.f);
            ((signed char*)&q)[j] = (signed char)(int)rv;
        }
        *reinterpret_cast<char4*>(g_qw + (tap*COUT + cout)*CIN + cin4*4) = q;
    }
    __syncthreads();
    if (tid == 0) { __threadfence(); atomicAdd(&g_ccq, 1u); }

    // -------- phase 1d: wait ccq, issue Bs staging (half-N) -----------------
    if (tid == 0) {
        while (VREAD(g_ccq) < (r + 1u) * 256u) {}
        __threadfence();
    }
    __syncthreads();
    for (int idx = tid; idx < KTAPS*64*4; idx += NTHR) {   // 2304
        const int rr = idx >> 2, q = idx & 3;              // rr = tap*64+col
        const int tap = rr >> 6, col = rr & 63;
        cp16(Bs + rr*ROWB + q*16,
             g_qw + ((tap << 7) + (nh << 6) + col)*CIN + q*16);
    }
    asm volatile("cp.async.commit_group;\n");

    // -------- phase 1e: wait ccx (the real barrier), quantize regs -> qwin --
    if (tid == 0) {
        while (VREAD(g_ccx) < (r + 1u) * 256u) {}
        __threadfence();
        s_sc[0] = __uint_as_float(VREAD(g_mx));
    }
    __syncthreads();
    const float fmx = s_sc[0];
    const float invx = __fdiv_rn(127.0f, fmx);
    const float oscale = __fmul_rn(__fdiv_rn(fmx, 127.0f), __fdiv_rn(fmw, 127.0f));

    #pragma unroll
    for (int u = 0; u < 6; u++) {
        const int unit = u*NTHR + tid;
        const int c4   = unit / 192;
        const int cell = unit - c4*192;
        const int yy   = cell >> 5, gx = cell & 31;
        const int gy   = y0 + yy;
        if ((unsigned)gy < 32u) {
            char4 q;
            #pragma unroll
            for (int j = 0; j < 4; j++) {
                float rv = rintf(xv[u][j] * invx);
                rv = fminf(fmaxf(rv, -127.f), 127.f);
                ((signed char*)&q)[j] = (signed char)(int)rv;
            }
            *reinterpret_cast<unsigned*>(qwin + yy*QROW + (gx+1)*ROWB + c4*4) =
                *reinterpret_cast<unsigned*>(&q);
        }
    }
    asm volatile("cp.async.wait_group 0;\n");
    __syncthreads();                               // Bs + qwin complete

    // -------- phase 3: MMA, 16 warps, warp tile 32x16 -----------------------
    const int g     = lane >> 2;
    const int tg    = lane & 3;
    const int warpM = wid >> 2;     // 0..3 -> 32 rows
    const int warpN = wid & 3;      // 0..3 -> 16 couts (of this half)

    int acc[2][2][4];
    #pragma unroll
    for (int mi = 0; mi < 2; mi++)
        #pragma unroll
        for (int nb = 0; nb < 2; nb++)
            #pragma unroll
            for (int rr = 0; rr < 4; rr++) acc[mi][nb][rr] = 0;

    const uint32_t aoff = ((lane & 7) + ((lane >> 3) & 1)*8)*ROWB + (lane >> 4)*16;
    const uint32_t boff = (lane & 7)*ROWB + ((lane >> 3) & 1)*16;
    const uint32_t abase = smem_u32(qwin) + (uint32_t)(warpM*QROW) + aoff;
    const uint32_t bbase = smem_u32(Bs) + (uint32_t)(warpN*16*ROWB) + boff;

    #pragma unroll
    for (int tap = 0; tap < KTAPS; tap++) {
        const int kh = tap / 3, kw = tap % 3;
        const uint32_t at = abase + (uint32_t)(kh*QROW + kw*ROWB);
        const uint32_t bt = bbase + (uint32_t)(tap*(64*ROWB));
        #pragma unroll
        for (int kk = 0; kk < 2; kk++) {
            const uint32_t ko = kk * 32;
            unsigned a[2][4];
            ldsm4(a[0], at + ko);
            ldsm4(a[1], at + 16*ROWB + ko);
            unsigned b[2][2];
            ldsm2(b[0], bt + ko);
            ldsm2(b[1], bt + 8*ROWB + ko);
            #pragma unroll
            for (int nb = 0; nb < 2; nb++) {
                mma_s8(acc[0][nb], a[0], b[nb][0], b[nb][1]);
                mma_s8(acc[1][nb], a[1], b[nb][0], b[nb][1]);
            }
        }
    }
    __syncthreads();

    // -------- epilogue: smem transpose -> coalesced float4 stores -----------
    float* smf = reinterpret_cast<float*>(sm);     // 64*132*4 = 33792 <= Bs
    #pragma unroll
    for (int mi = 0; mi < 2; mi++) {
        #pragma unroll
        for (int nb = 0; nb < 2; nb++) {
            #pragma unroll
            for (int rr = 0; rr < 4; rr++) {
                const int row = warpM*32 + mi*16 + g + ((rr >> 1) * 8);
                const int col = warpN*16 + nb*8 + tg*2 + (rr & 1);
                smf[col*EP_STRIDE + row] = (float)acc[mi][nb][rr];
            }
        }
    }
    __syncthreads();
    {
        #pragma unroll
        for (int co = 0; co < 4; co++) {
            const int cl   = wid*4 + co;           // 0..63
            const int cout = (nh << 6) + cl;
            const float bz = bias[cout];
            const float* sp = smf + cl*EP_STRIDE + lane*4;
            float4 v = make_float4(oscale*sp[0] + bz, oscale*sp[1] + bz,
                                   oscale*sp[2] + bz, oscale*sp[3] + bz);
            *reinterpret_cast<float4*>(
                out + ((size_t)bi*COUT + cout)*L + l0 + lane*4) = v;
        }
    }
}

// ---------------------------------------------------------------------------
extern "C" void kernel_launch(void* const* d_in, const int* in_sizes, int n_in,
                              void* d_out, int out_size) {
    const float* x  = (const float*)d_in[0];   // [16,64,32,32]
    const float* w  = (const float*)d_in[1];   // [128,64,3,3]
    const float* bs = (const float*)d_in[2];   // [128]
    float* out = (float*)d_out;                // [16,128,32,32]

    cudaFuncSetAttribute(kfused, cudaFuncAttributeMaxDynamicSharedMemorySize,
                         SMEM_TOT);
    kfused<<<NBLK, NTHR, SMEM_TOT>>>(x, w, bs, out);
}